// round 1
// baseline (speedup 1.0000x reference)
#include <cuda_runtime.h>
#include <cuda_bf16.h>

// Winograd F(4x4,3x3)-style with filter already in 6x6 transform domain.
// N=16, C=64 in/out, H=W=128, pad=1 -> nt=32 tiles per dim, 4x4 output tile.
//
// Fused single kernel:
//   CTA = (n, tile_row tp, tile-col block tqb of 8 tiles)
//   grid = (4, 32, 16) = 2048 CTAs, 256 threads each.
//   Per cin: stage 6x34 input patch + 64x36 weight slice in SMEM,
//   compute U = BT @ D (per column), V = U @ BT^T (per tile),
//   each thread accumulates (1 cout) x (2 tiles) x 36 points in registers.
//   Epilogue: Y = AT @ M @ AT^T + bias, float4 stores.

#define NN 16
#define CC 64
#define HH 128

__global__ __launch_bounds__(256, 2)
void winograd_fused_kernel(const float* __restrict__ x,
                           const float* __restrict__ w,
                           const float* __restrict__ bias,
                           float* __restrict__ y)
{
    __shared__ float sD[6][34];
    __shared__ float sU[6][34];
    __shared__ float sV[8][36];
    __shared__ float sW[64 * 36];

    const int tid = threadIdx.x;
    const int tqb = blockIdx.x;   // 0..3  (8 tiles each)
    const int tp  = blockIdx.y;   // 0..31 (tile row)
    const int n   = blockIdx.z;   // 0..15

    const int cout = tid >> 2;    // 0..63
    const int grp  = tid & 3;     // 0..3
    const int t0 = grp * 2;
    const int t1 = grp * 2 + 1;

    float acc0[36], acc1[36];
#pragma unroll
    for (int i = 0; i < 36; i++) { acc0[i] = 0.f; acc1[i] = 0.f; }

    const int r0 = tp * 4 - 1;
    const int c0 = tqb * 32 - 1;

    for (int cin = 0; cin < CC; ++cin) {
        // ---- stage input patch (6 x 34, zero-padded at borders) ----
        {
            const float* xp = x + ((size_t)(n * CC + cin)) * (HH * HH);
            if (tid < 204) {
                int i = tid / 34;
                int j = tid - i * 34;
                int r = r0 + i, c = c0 + j;
                float v = 0.f;
                if ((unsigned)r < HH && (unsigned)c < HH) v = xp[r * HH + c];
                sD[i][j] = v;
            }
            // ---- stage weight slice: all couts for this cin (64 x 36) ----
            const float* wp = w + (size_t)cin * 36;
#pragma unroll
            for (int k = 0; k < 9; k++) {
                int l = tid + k * 256;
                int co = l / 36;
                int ab = l - co * 36;
                sW[l] = wp[(size_t)co * (CC * 36) + ab];
            }
        }
        __syncthreads();

        // ---- U[a][col] = sum_i BT[a][i] * D[i][col], 34 columns ----
        if (tid < 34) {
            float d0 = sD[0][tid], d1 = sD[1][tid], d2 = sD[2][tid];
            float d3 = sD[3][tid], d4 = sD[4][tid], d5 = sD[5][tid];
            sU[0][tid] =  4.f * d0 - 5.f * d2 + d4;
            sU[1][tid] = -4.f * d1 - 4.f * d2 + d3 + d4;
            sU[2][tid] =  4.f * d1 - 4.f * d2 - d3 + d4;
            sU[3][tid] = -2.f * d1 -       d2 + 2.f * d3 + d4;
            sU[4][tid] =  2.f * d1 -       d2 - 2.f * d3 + d4;
            sU[5][tid] =  4.f * d1 - 5.f * d3 + d5;
        }
        __syncthreads();

        // ---- V[t][a][b] = sum_j U[a][t*4+j] * BT[b][j], 8 tiles x 6 a ----
        if (tid < 48) {
            int t = tid / 6;
            int a = tid - t * 6;
            const float* u = &sU[a][t * 4];
            float u0 = u[0], u1 = u[1], u2 = u[2], u3 = u[3], u4 = u[4], u5 = u[5];
            float* vv = &sV[t][a * 6];
            vv[0] =  4.f * u0 - 5.f * u2 + u4;
            vv[1] = -4.f * u1 - 4.f * u2 + u3 + u4;
            vv[2] =  4.f * u1 - 4.f * u2 - u3 + u4;
            vv[3] = -2.f * u1 -       u2 + 2.f * u3 + u4;
            vv[4] =  2.f * u1 -       u2 - 2.f * u3 + u4;
            vv[5] =  4.f * u1 - 5.f * u3 + u5;
        }
        __syncthreads();

        // ---- accumulate: acc[tile][ab] += W[cout][ab] * V[tile][ab] ----
        {
            const float4* Wv = (const float4*)(&sW[cout * 36]);
            const float4* V0 = (const float4*)(&sV[t0][0]);
            const float4* V1 = (const float4*)(&sV[t1][0]);
#pragma unroll
            for (int k = 0; k < 9; k++) {
                float4 wv = Wv[k];
                float4 v0 = V0[k];
                float4 v1 = V1[k];
                acc0[4 * k + 0] += wv.x * v0.x;
                acc0[4 * k + 1] += wv.y * v0.y;
                acc0[4 * k + 2] += wv.z * v0.z;
                acc0[4 * k + 3] += wv.w * v0.w;
                acc1[4 * k + 0] += wv.x * v1.x;
                acc1[4 * k + 1] += wv.y * v1.y;
                acc1[4 * k + 2] += wv.z * v1.z;
                acc1[4 * k + 3] += wv.w * v1.w;
            }
        }
        __syncthreads();
    }

    // ---- epilogue: Y = AT @ M @ AT^T + bias ----
    const float bval = bias[cout];
    float* ybase = y + ((size_t)(n * CC + cout)) * (HH * HH);

    auto store_tile = [&](const float (&acc)[36], int t) {
        float tmp[24];
#pragma unroll
        for (int bcol = 0; bcol < 6; bcol++) {
            float m0 = acc[bcol],      m1 = acc[6 + bcol],  m2 = acc[12 + bcol];
            float m3 = acc[18 + bcol], m4 = acc[24 + bcol], m5 = acc[30 + bcol];
            tmp[0 * 6 + bcol] = m0 + m1 + m2 + m3 + m4;
            tmp[1 * 6 + bcol] = m1 - m2 + 2.f * m3 - 2.f * m4;
            tmp[2 * 6 + bcol] = m1 + m2 + 4.f * m3 + 4.f * m4;
            tmp[3 * 6 + bcol] = m1 - m2 + 8.f * m3 - 8.f * m4 + m5;
        }
        int wcol = (tqb * 8 + t) * 4;
#pragma unroll
        for (int xr = 0; xr < 4; xr++) {
            float T0 = tmp[xr * 6 + 0], T1 = tmp[xr * 6 + 1], T2 = tmp[xr * 6 + 2];
            float T3 = tmp[xr * 6 + 3], T4 = tmp[xr * 6 + 4], T5 = tmp[xr * 6 + 5];
            float4 o;
            o.x = T0 + T1 + T2 + T3 + T4 + bval;
            o.y = T1 - T2 + 2.f * T3 - 2.f * T4 + bval;
            o.z = T1 + T2 + 4.f * T3 + 4.f * T4 + bval;
            o.w = T1 - T2 + 8.f * T3 - 8.f * T4 + T5 + bval;
            *(float4*)(ybase + (size_t)(tp * 4 + xr) * HH + wcol) = o;
        }
    };
    store_tile(acc0, t0);
    store_tile(acc1, t1);
}

extern "C" void kernel_launch(void* const* d_in, const int* in_sizes, int n_in,
                              void* d_out, int out_size) {
    const float* x    = (const float*)d_in[0];   // 16x64x128x128
    const float* wgt  = (const float*)d_in[1];   // 64x64x6x6 (transform-domain)
    const float* bias = (const float*)d_in[2];   // 64
    float* y = (float*)d_out;                    // 16x64x128x128

    dim3 grid(4, 32, 16);
    dim3 block(256);
    winograd_fused_kernel<<<grid, block>>>(x, wgt, bias, y);
}

// round 2
// speedup vs baseline: 1.2835x; 1.2835x over previous
#include <cuda_runtime.h>
#include <cuda_bf16.h>

// Winograd F(4x4,3x3) with filter already in 6x6 transform domain.
// N=16, Cin=Cout=64, H=W=128, pad=1, nt=32.
//
// CTA = (cout-quarter ch of 16 couts, tile-row tp, image n). 256 threads.
// Loop cin:
//   stage D[6][130] + W[16][36->48pad] (prefetched LDGs),
//   U = BT@D (130 cols), V per tile (36 pts x 32 tiles -> sV[p][t]),
//   GEMM: warp w: cg=w&1 (8 couts), pg=w>>2.. (9 points), lane=tile.
//   Thread acc[8 couts][9 points]; V reads coalesced LDS.32, W reads broadcast
//   vector LDS (1 wavefront each).
// Epilogue: 4 chunks of 4 couts via sM[4][36][32], A-transform + bias, float4 stores.

#define HH 128

__global__ __launch_bounds__(256, 2)
void winograd_v2_kernel(const float* __restrict__ x,
                        const float* __restrict__ w,
                        const float* __restrict__ bias,
                        float* __restrict__ y)
{
    __shared__ float sD[6][132];
    __shared__ float sU[6][132];
    __shared__ float sV[36][32];
    __shared__ float sW[16 * 48];
    __shared__ float sM[4][36][32];

    const int tid = threadIdx.x;
    const int ch  = blockIdx.x;   // cout quarter: couts ch*16 .. ch*16+15
    const int tp  = blockIdx.y;   // tile row 0..31
    const int n   = blockIdx.z;   // image 0..15

    // GEMM thread mapping
    const int t  = tid & 31;      // lane = tile column
    const int wp = tid >> 5;      // warp 0..7
    const int cg = wp & 1;        // cout group (8 couts)
    const int pg = wp >> 1;       // point group (9 points)

    const int r0 = tp * 4 - 1;    // first input row of strip

    float acc[8][9];
#pragma unroll
    for (int i = 0; i < 8; i++)
#pragma unroll
        for (int j = 0; j < 9; j++) acc[i][j] = 0.f;

    const float* xn = x + (size_t)n * 64 * HH * HH;
    const float* wb = w + (size_t)(ch * 16) * (64 * 36);

    // ---- prefetch cin = 0 ----
    float dreg[4];
    float wreg[3];
    {
        const float* xp = xn;  // cin 0
#pragma unroll
        for (int k = 0; k < 4; k++) {
            int l = tid + 256 * k;
            float v = 0.f;
            if (l < 780) {
                int i = l / 130;
                int j = l - i * 130;
                int r = r0 + i, c = j - 1;
                if ((unsigned)r < HH && (unsigned)c < HH) v = xp[r * HH + c];
            }
            dreg[k] = v;
        }
#pragma unroll
        for (int k = 0; k < 3; k++) {
            int l = tid + 256 * k;
            wreg[k] = (l < 576) ? wb[(l / 36) * (64 * 36) + (l % 36)] : 0.f;
        }
    }

    for (int cin = 0; cin < 64; ++cin) {
        __syncthreads();   // previous GEMM done; sD/sU/sV/sW free

        // ---- store staged data ----
#pragma unroll
        for (int k = 0; k < 4; k++) {
            int l = tid + 256 * k;
            if (l < 780) {
                int i = l / 130;
                int j = l - i * 130;
                sD[i][j] = dreg[k];
            }
        }
#pragma unroll
        for (int k = 0; k < 3; k++) {
            int l = tid + 256 * k;
            if (l < 576) {
                int co = l / 36;
                int p  = l - co * 36;
                int g  = p / 9;
                sW[co * 48 + g * 12 + (p - 9 * g)] = wreg[k];
            }
        }

        // ---- prefetch next cin (latency hides under transform + GEMM) ----
        if (cin + 1 < 64) {
            const float* xp = xn + (size_t)(cin + 1) * HH * HH;
#pragma unroll
            for (int k = 0; k < 4; k++) {
                int l = tid + 256 * k;
                float v = 0.f;
                if (l < 780) {
                    int i = l / 130;
                    int j = l - i * 130;
                    int r = r0 + i, c = j - 1;
                    if ((unsigned)r < HH && (unsigned)c < HH) v = xp[r * HH + c];
                }
                dreg[k] = v;
            }
            const float* wp2 = wb + (size_t)(cin + 1) * 36;
#pragma unroll
            for (int k = 0; k < 3; k++) {
                int l = tid + 256 * k;
                wreg[k] = (l < 576) ? wp2[(l / 36) * (64 * 36) + (l % 36)] : 0.f;
            }
        }

        __syncthreads();

        // ---- U = BT @ D, per column (130 columns) ----
        if (tid < 130) {
            float d0 = sD[0][tid], d1 = sD[1][tid], d2 = sD[2][tid];
            float d3 = sD[3][tid], d4 = sD[4][tid], d5 = sD[5][tid];
            sU[0][tid] =  4.f * d0 - 5.f * d2 + d4;
            sU[1][tid] = -4.f * d1 - 4.f * d2 + d3 + d4;
            sU[2][tid] =  4.f * d1 - 4.f * d2 - d3 + d4;
            sU[3][tid] = -2.f * d1 -       d2 + 2.f * d3 + d4;
            sU[4][tid] =  2.f * d1 -       d2 - 2.f * d3 + d4;
            sU[5][tid] =  4.f * d1 - 5.f * d3 + d5;
        }

        __syncthreads();

        // ---- V: per (a, tile): 6 outputs from U row a ----
        if (tid < 192) {
            int a  = tid >> 5;     // warp = row a (conflict-free vec loads)
            int tt = tid & 31;
            float4 u03 = *(const float4*)&sU[a][4 * tt];
            float2 u45 = *(const float2*)&sU[a][4 * tt + 4];
            float u0 = u03.x, u1 = u03.y, u2 = u03.z, u3 = u03.w;
            float u4 = u45.x, u5 = u45.y;
            sV[a * 6 + 0][tt] =  4.f * u0 - 5.f * u2 + u4;
            sV[a * 6 + 1][tt] = -4.f * u1 - 4.f * u2 + u3 + u4;
            sV[a * 6 + 2][tt] =  4.f * u1 - 4.f * u2 - u3 + u4;
            sV[a * 6 + 3][tt] = -2.f * u1 -       u2 + 2.f * u3 + u4;
            sV[a * 6 + 4][tt] =  2.f * u1 -       u2 - 2.f * u3 + u4;
            sV[a * 6 + 5][tt] =  4.f * u1 - 5.f * u3 + u5;
        }

        __syncthreads();

        // ---- GEMM: acc[co][k] += W[cg*8+co][pg*9+k] * V[pg*9+k][t] ----
        {
            float v[9];
#pragma unroll
            for (int k = 0; k < 9; k++) v[k] = sV[pg * 9 + k][t];

            const float* wrow = &sW[cg * 8 * 48 + pg * 12];
#pragma unroll
            for (int co = 0; co < 8; co++) {
                const float* wr = wrow + co * 48;
                float4 w0 = *(const float4*)wr;        // broadcast, 1 wavefront
                float4 w1 = *(const float4*)(wr + 4);  // broadcast
                float  w8 = wr[8];                     // broadcast
                acc[co][0] += w0.x * v[0];
                acc[co][1] += w0.y * v[1];
                acc[co][2] += w0.z * v[2];
                acc[co][3] += w0.w * v[3];
                acc[co][4] += w1.x * v[4];
                acc[co][5] += w1.y * v[5];
                acc[co][6] += w1.z * v[6];
                acc[co][7] += w1.w * v[7];
                acc[co][8] += w8   * v[8];
            }
        }
    }

    // ================= epilogue: 4 chunks of 4 couts =================
#pragma unroll 1
    for (int c4 = 0; c4 < 4; c4++) {
        // writers: warps with cg == c4>>1 hold couts [4*c4, 4*c4+4)
        if (cg == (c4 >> 1)) {
            int base = 4 * (c4 & 1);
#pragma unroll
            for (int cl = 0; cl < 4; cl++) {
#pragma unroll
                for (int k = 0; k < 9; k++) {
                    sM[cl][pg * 9 + k][t] = acc[base + cl][k];
                }
            }
        }
        __syncthreads();

        if (tid < 128) {
            int cl = tid >> 5;
            int tt = tid & 31;
            int co_g = ch * 16 + c4 * 4 + cl;
            float bval = bias[co_g];

            float m[36];
#pragma unroll
            for (int p = 0; p < 36; p++) m[p] = sM[cl][p][tt];

            // Z = AT @ M  (4 x 6)
            float z[24];
#pragma unroll
            for (int b = 0; b < 6; b++) {
                float m0 = m[b], m1 = m[6 + b], m2 = m[12 + b];
                float m3 = m[18 + b], m4 = m[24 + b], m5 = m[30 + b];
                z[0 * 6 + b] = m0 + m1 + m2 + m3 + m4;
                z[1 * 6 + b] = m1 - m2 + 2.f * m3 - 2.f * m4;
                z[2 * 6 + b] = m1 + m2 + 4.f * m3 + 4.f * m4;
                z[3 * 6 + b] = m1 - m2 + 8.f * m3 - 8.f * m4 + m5;
            }

            float* ybase = y + (((size_t)(n * 64 + co_g)) * HH + tp * 4) * HH + tt * 4;
#pragma unroll
            for (int xr = 0; xr < 4; xr++) {
                float T0 = z[xr * 6 + 0], T1 = z[xr * 6 + 1], T2 = z[xr * 6 + 2];
                float T3 = z[xr * 6 + 3], T4 = z[xr * 6 + 4], T5 = z[xr * 6 + 5];
                float4 o;
                o.x = T0 + T1 + T2 + T3 + T4 + bval;
                o.y = T1 - T2 + 2.f * T3 - 2.f * T4 + bval;
                o.z = T1 + T2 + 4.f * T3 + 4.f * T4 + bval;
                o.w = T1 - T2 + 8.f * T3 - 8.f * T4 + T5 + bval;
                *(float4*)(ybase + (size_t)xr * HH) = o;
            }
        }
        __syncthreads();
    }
}

extern "C" void kernel_launch(void* const* d_in, const int* in_sizes, int n_in,
                              void* d_out, int out_size) {
    const float* x    = (const float*)d_in[0];   // 16x64x128x128
    const float* wgt  = (const float*)d_in[1];   // 64x64x6x6 (transform domain)
    const float* bias = (const float*)d_in[2];   // 64
    float* y = (float*)d_out;                    // 16x64x128x128

    dim3 grid(4, 32, 16);   // (cout quarter, tile row, image)
    dim3 block(256);
    winograd_v2_kernel<<<grid, block>>>(x, wgt, bias, y);
}